// round 2
// baseline (speedup 1.0000x reference)
#include <cuda_runtime.h>
#include <cuda_bf16.h>

#define N_NODES 50000
#define N_EDGES 800000
#define N_GRAPHS 512
#define IN_CH 128
#define HID 64     // HID_CH == OUT_CH == 64

// ---------------- scratch (device globals; no allocs allowed) ----------------
__device__ float g_xw[N_NODES * HID];    // x @ W1
__device__ float g_h1[N_NODES * HID];    // conv1 out (pre-relu)
__device__ float g_h2[N_NODES * HID];    // relu(h1) @ W2
__device__ float g_h3[N_NODES * HID];    // conv2 out
__device__ float g_deg[N_NODES];
__device__ float g_dinv[N_NODES];
__device__ float g_coef[N_EDGES];
__device__ float g_pool[N_GRAPHS * HID];
__device__ float g_cnt[N_GRAPHS];

// ---------------- degree / norm ----------------
__global__ void deg_kernel(const int* __restrict__ dst,
                           const float* __restrict__ ew) {
    int e = blockIdx.x * blockDim.x + threadIdx.x;
    if (e < N_EDGES) atomicAdd(&g_deg[dst[e]], ew[e]);
}

__global__ void dinv_kernel() {
    int i = blockIdx.x * blockDim.x + threadIdx.x;
    if (i < N_NODES) {
        float d = g_deg[i] + 1.0f;  // +1 self loop weight; always > 0
        g_dinv[i] = rsqrtf(d);
    }
}

__global__ void coef_kernel(const int* __restrict__ src,
                            const int* __restrict__ dst,
                            const float* __restrict__ ew) {
    int e = blockIdx.x * blockDim.x + threadIdx.x;
    if (e < N_EDGES) {
        g_coef[e] = g_dinv[src[e]] * ew[e] * g_dinv[dst[e]];
    }
}

// ---------------- GEMM 1: [N,128] @ [128,64] -> g_xw ----------------
__global__ void gemm1_kernel(const float* __restrict__ x,
                             const float* __restrict__ W) {
    __shared__ float Ws[IN_CH * HID];
    __shared__ float Xs[4 * IN_CH];
    for (int i = threadIdx.x; i < IN_CH * HID; i += 256) Ws[i] = W[i];
    int row0 = blockIdx.x * 4;
    for (int i = threadIdx.x; i < 4 * IN_CH; i += 256)
        Xs[i] = x[(row0 + i / IN_CH) * IN_CH + (i % IN_CH)];
    __syncthreads();
    int r = threadIdx.x >> 6;       // 0..3
    int c = threadIdx.x & 63;       // 0..63
    float acc = 0.0f;
    #pragma unroll
    for (int k = 0; k < IN_CH; k++)
        acc += Xs[r * IN_CH + k] * Ws[k * HID + c];
    g_xw[(row0 + r) * HID + c] = acc;
}

// ---------------- GEMM 2: relu(g_h1) [N,64] @ [64,64] -> g_h2 ----------------
__global__ void gemm2_kernel(const float* __restrict__ W) {
    __shared__ float Ws[HID * HID];
    __shared__ float Xs[4 * HID];
    for (int i = threadIdx.x; i < HID * HID; i += 256) Ws[i] = W[i];
    int row0 = blockIdx.x * 4;
    for (int i = threadIdx.x; i < 4 * HID; i += 256)
        Xs[i] = fmaxf(g_h1[(row0 + i / HID) * HID + (i % HID)], 0.0f);
    __syncthreads();
    int r = threadIdx.x >> 6;
    int c = threadIdx.x & 63;
    float acc = 0.0f;
    #pragma unroll
    for (int k = 0; k < HID; k++)
        acc += Xs[r * HID + k] * Ws[k * HID + c];
    g_h2[(row0 + r) * HID + c] = acc;
}

// ---------------- conv init: out = dinv^2 * in + b (self-loop + bias) -------
__global__ void init_kernel(const float* __restrict__ in,
                            float* __restrict__ out,
                            const float* __restrict__ b) {
    int idx = blockIdx.x * blockDim.x + threadIdx.x;
    if (idx < N_NODES * HID) {
        int i = idx >> 6;
        int c = idx & 63;
        float d = g_dinv[i];
        out[idx] = d * d * in[idx] + b[c];
    }
}

// ---------------- edge scatter: out[dst] += coef * in[src] ------------------
// 16 threads per edge, float4 gather + 4 scalar atomics.
__global__ void scatter_kernel(const int* __restrict__ src,
                               const int* __restrict__ dst,
                               const float* __restrict__ in,
                               float* __restrict__ out) {
    long long idx = (long long)blockIdx.x * blockDim.x + threadIdx.x;
    if (idx >= (long long)N_EDGES * 16) return;
    int e  = (int)(idx >> 4);
    int c4 = (int)(idx & 15) * 4;
    float cf = g_coef[e];
    int s = src[e];
    int d = dst[e];
    float4 v = *(const float4*)(in + (long long)s * HID + c4);
    float* o = out + (long long)d * HID + c4;
    atomicAdd(o + 0, cf * v.x);
    atomicAdd(o + 1, cf * v.y);
    atomicAdd(o + 2, cf * v.z);
    atomicAdd(o + 3, cf * v.w);
}

// ---------------- pooling: segment mean over graphs -------------------------
__global__ void pool_kernel(const int* __restrict__ batch) {
    int idx = blockIdx.x * blockDim.x + threadIdx.x;
    if (idx < N_NODES * HID) {
        int i = idx >> 6;
        int c = idx & 63;
        int g = batch[i];
        atomicAdd(&g_pool[g * HID + c], g_h3[idx]);
        if (c == 0) atomicAdd(&g_cnt[g], 1.0f);
    }
}

// ---------------- head: (pool/cnt) @ LW1 + Lb1, @ LW2 + Lb2 -----------------
__global__ void head_kernel(const float* __restrict__ LW1,
                            const float* __restrict__ Lb1,
                            const float* __restrict__ LW2,
                            const float* __restrict__ Lb2,
                            float* __restrict__ out) {
    int g = blockIdx.x;
    int t = threadIdx.x;  // 32 threads
    __shared__ float p[HID];
    __shared__ float h[32];
    float cnt = fmaxf(g_cnt[g], 1.0f);
    p[t]      = g_pool[g * HID + t] / cnt;
    p[t + 32] = g_pool[g * HID + 32 + t] / cnt;
    __syncwarp();
    float acc = Lb1[t];
    #pragma unroll
    for (int k = 0; k < HID; k++) acc += p[k] * LW1[k * 32 + t];
    h[t] = acc;
    __syncwarp();
    if (t < 10) {
        float o = Lb2[t];
        #pragma unroll
        for (int j = 0; j < 32; j++) o += h[j] * LW2[j * 10 + t];
        out[g * 10 + t] = o;
    }
}

// ---------------- launch ----------------
extern "C" void kernel_launch(void* const* d_in, const int* in_sizes, int n_in,
                              void* d_out, int out_size) {
    const float* x     = (const float*)d_in[0];
    const int*   ei    = (const int*)d_in[1];   // [2, E] int32 (JAX x64 disabled)
    const float* ew    = (const float*)d_in[2];
    const int*   batch = (const int*)d_in[3];   // [N] int32
    const float* W1    = (const float*)d_in[4];
    const float* b1    = (const float*)d_in[5];
    const float* W2    = (const float*)d_in[6];
    const float* b2    = (const float*)d_in[7];
    const float* LW1   = (const float*)d_in[8];
    const float* Lb1   = (const float*)d_in[9];
    const float* LW2   = (const float*)d_in[10];
    const float* Lb2   = (const float*)d_in[11];
    float* out = (float*)d_out;

    const int* src = ei;
    const int* dst = ei + N_EDGES;

    void *p_deg, *p_pool, *p_cnt;
    cudaGetSymbolAddress(&p_deg,  g_deg);
    cudaGetSymbolAddress(&p_pool, g_pool);
    cudaGetSymbolAddress(&p_cnt,  g_cnt);
    cudaMemsetAsync(p_deg,  0, N_NODES * sizeof(float));
    cudaMemsetAsync(p_pool, 0, N_GRAPHS * HID * sizeof(float));
    cudaMemsetAsync(p_cnt,  0, N_GRAPHS * sizeof(float));

    // degree & normalization coefficients
    deg_kernel<<<(N_EDGES + 255) / 256, 256>>>(dst, ew);
    dinv_kernel<<<(N_NODES + 255) / 256, 256>>>();
    coef_kernel<<<(N_EDGES + 255) / 256, 256>>>(src, dst, ew);

    float *xw, *h1, *h2, *h3;
    cudaGetSymbolAddress((void**)&xw, g_xw);
    cudaGetSymbolAddress((void**)&h1, g_h1);
    cudaGetSymbolAddress((void**)&h2, g_h2);
    cudaGetSymbolAddress((void**)&h3, g_h3);

    // conv1
    gemm1_kernel<<<N_NODES / 4, 256>>>(x, W1);
    init_kernel<<<(N_NODES * HID + 255) / 256, 256>>>(xw, h1, b1);
    scatter_kernel<<<(int)(((long long)N_EDGES * 16 + 255) / 256), 256>>>(src, dst, xw, h1);

    // conv2 (relu fused into gemm2's operand load)
    gemm2_kernel<<<N_NODES / 4, 256>>>(W2);
    init_kernel<<<(N_NODES * HID + 255) / 256, 256>>>(h2, h3, b2);
    scatter_kernel<<<(int)(((long long)N_EDGES * 16 + 255) / 256), 256>>>(src, dst, h2, h3);

    // pooling + head
    pool_kernel<<<(N_NODES * HID + 255) / 256, 256>>>(batch);
    head_kernel<<<N_GRAPHS, 32>>>(LW1, Lb1, LW2, Lb2, out);
}

// round 3
// speedup vs baseline: 1.8439x; 1.8439x over previous
#include <cuda_runtime.h>
#include <cuda_bf16.h>

#define N_NODES 50000
#define N_EDGES 800000
#define N_GRAPHS 512
#define IN_CH 128
#define HID 64     // HID_CH == OUT_CH == 64

// ---------------- scratch (device globals; no allocs allowed) ----------------
__device__ float g_xw[N_NODES * HID];    // x @ W1
__device__ float g_h1[N_NODES * HID];    // conv1 out (pre-relu)
__device__ float g_h2[N_NODES * HID];    // relu(h1) @ W2
__device__ float g_h3[N_NODES * HID];    // conv2 out
__device__ float g_deg[N_NODES];
__device__ float g_dinv[N_NODES];
__device__ float g_coef[N_EDGES];
__device__ float g_pool[N_GRAPHS * HID];
__device__ float g_cnt[N_GRAPHS];

// vectorized fp32 reduction (sm_90+): one L2 atomic op per 16 bytes
__device__ __forceinline__ void red_add_v4(float* addr, float a, float b,
                                           float c, float d) {
    asm volatile("red.global.add.v4.f32 [%0], {%1, %2, %3, %4};"
                 :: "l"(addr), "f"(a), "f"(b), "f"(c), "f"(d) : "memory");
}

// ---------------- degree / norm ----------------
__global__ void deg_kernel(const int* __restrict__ dst,
                           const float* __restrict__ ew) {
    int e = blockIdx.x * blockDim.x + threadIdx.x;
    if (e < N_EDGES) atomicAdd(&g_deg[dst[e]], ew[e]);
}

__global__ void dinv_kernel() {
    int i = blockIdx.x * blockDim.x + threadIdx.x;
    if (i < N_NODES) {
        float d = g_deg[i] + 1.0f;  // +1 self loop weight; always > 0
        g_dinv[i] = rsqrtf(d);
    }
}

__global__ void coef_kernel(const int* __restrict__ src,
                            const int* __restrict__ dst,
                            const float* __restrict__ ew) {
    int e = blockIdx.x * blockDim.x + threadIdx.x;
    if (e < N_EDGES) {
        g_coef[e] = g_dinv[src[e]] * ew[e] * g_dinv[dst[e]];
    }
}

// ---------------- GEMM 1: [N,128] @ [128,64] -> g_xw, g_h1 ------------------
// 16 rows/block, thread = (row, 4 cols). Fused self-loop+bias epilogue.
#define G1_ROWS 16
#define XS1_LD (IN_CH + 1)   // padded stride: kills bank conflict on Xs
__global__ void gemm1_kernel(const float* __restrict__ x,
                             const float* __restrict__ W,
                             const float* __restrict__ b) {
    __shared__ float Ws[IN_CH * HID];        // 32 KB
    __shared__ float Xs[G1_ROWS * XS1_LD];   // ~8 KB
    // stage W (float4)
    for (int i = threadIdx.x; i < IN_CH * HID / 4; i += 256)
        *(float4*)&Ws[i * 4] = *(const float4*)&W[i * 4];
    // stage X rows (coalesced read, padded smem write)
    int row0 = blockIdx.x * G1_ROWS;
    for (int i = threadIdx.x; i < G1_ROWS * IN_CH; i += 256) {
        int r = i >> 7, c = i & 127;
        Xs[r * XS1_LD + c] = x[(long long)(row0 + r) * IN_CH + c];
    }
    __syncthreads();
    int r  = threadIdx.x >> 4;        // 0..15
    int c4 = (threadIdx.x & 15) * 4;  // 0,4,...,60
    float4 acc = make_float4(0.f, 0.f, 0.f, 0.f);
    #pragma unroll
    for (int k = 0; k < IN_CH; k++) {
        float xv = Xs[r * XS1_LD + k];
        float4 w = *(const float4*)&Ws[k * HID + c4];
        acc.x += xv * w.x; acc.y += xv * w.y;
        acc.z += xv * w.z; acc.w += xv * w.w;
    }
    int node = row0 + r;
    *(float4*)&g_xw[node * HID + c4] = acc;
    float d = g_dinv[node];
    float dd = d * d;
    float4 bb = *(const float4*)&b[c4];
    float4 h = make_float4(dd * acc.x + bb.x, dd * acc.y + bb.y,
                           dd * acc.z + bb.z, dd * acc.w + bb.w);
    *(float4*)&g_h1[node * HID + c4] = h;
}

// ---------------- GEMM 2: relu(g_h1) [N,64] @ [64,64] -> g_h2, g_h3 ---------
#define XS2_LD (HID + 1)
__global__ void gemm2_kernel(const float* __restrict__ W,
                             const float* __restrict__ b) {
    __shared__ float Ws[HID * HID];          // 16 KB
    __shared__ float Xs[G1_ROWS * XS2_LD];
    for (int i = threadIdx.x; i < HID * HID / 4; i += 256)
        *(float4*)&Ws[i * 4] = *(const float4*)&W[i * 4];
    int row0 = blockIdx.x * G1_ROWS;
    for (int i = threadIdx.x; i < G1_ROWS * HID; i += 256) {
        int r = i >> 6, c = i & 63;
        Xs[r * XS2_LD + c] = fmaxf(g_h1[(row0 + r) * HID + c], 0.0f);
    }
    __syncthreads();
    int r  = threadIdx.x >> 4;
    int c4 = (threadIdx.x & 15) * 4;
    float4 acc = make_float4(0.f, 0.f, 0.f, 0.f);
    #pragma unroll
    for (int k = 0; k < HID; k++) {
        float xv = Xs[r * XS2_LD + k];
        float4 w = *(const float4*)&Ws[k * HID + c4];
        acc.x += xv * w.x; acc.y += xv * w.y;
        acc.z += xv * w.z; acc.w += xv * w.w;
    }
    int node = row0 + r;
    *(float4*)&g_h2[node * HID + c4] = acc;
    float d = g_dinv[node];
    float dd = d * d;
    float4 bb = *(const float4*)&b[c4];
    float4 h = make_float4(dd * acc.x + bb.x, dd * acc.y + bb.y,
                           dd * acc.z + bb.z, dd * acc.w + bb.w);
    *(float4*)&g_h3[node * HID + c4] = h;
}

// ---------------- edge scatter: out[dst] += coef * in[src] ------------------
// 16 threads per edge, float4 gather + one v4 vector atomic.
__global__ void scatter_kernel(const int* __restrict__ src,
                               const int* __restrict__ dst,
                               const float* __restrict__ in,
                               float* __restrict__ out) {
    int idx = blockIdx.x * blockDim.x + threadIdx.x;   // < 12.8M
    if (idx >= N_EDGES * 16) return;
    int e  = idx >> 4;
    int c4 = (idx & 15) * 4;
    float cf = g_coef[e];
    int s = src[e];
    int d = dst[e];
    float4 v = *(const float4*)(in + (long long)s * HID + c4);
    red_add_v4(out + (long long)d * HID + c4,
               cf * v.x, cf * v.y, cf * v.z, cf * v.w);
}

// ---------------- pooling: segment mean over graphs -------------------------
__global__ void pool_kernel(const int* __restrict__ batch) {
    int idx = blockIdx.x * blockDim.x + threadIdx.x;   // < 800k
    if (idx < N_NODES * 16) {
        int i  = idx >> 4;
        int c4 = (idx & 15) * 4;
        int g = batch[i];
        float4 v = *(const float4*)&g_h3[i * HID + c4];
        red_add_v4(&g_pool[g * HID + c4], v.x, v.y, v.z, v.w);
        if (c4 == 0) atomicAdd(&g_cnt[g], 1.0f);
    }
}

// ---------------- head: (pool/cnt) @ LW1 + Lb1, @ LW2 + Lb2 -----------------
__global__ void head_kernel(const float* __restrict__ LW1,
                            const float* __restrict__ Lb1,
                            const float* __restrict__ LW2,
                            const float* __restrict__ Lb2,
                            float* __restrict__ out) {
    int g = blockIdx.x;
    int t = threadIdx.x;  // 32 threads
    __shared__ float p[HID];
    __shared__ float h[32];
    float cnt = fmaxf(g_cnt[g], 1.0f);
    p[t]      = g_pool[g * HID + t] / cnt;
    p[t + 32] = g_pool[g * HID + 32 + t] / cnt;
    __syncwarp();
    float acc = Lb1[t];
    #pragma unroll
    for (int k = 0; k < HID; k++) acc += p[k] * LW1[k * 32 + t];
    h[t] = acc;
    __syncwarp();
    if (t < 10) {
        float o = Lb2[t];
        #pragma unroll
        for (int j = 0; j < 32; j++) o += h[j] * LW2[j * 10 + t];
        out[g * 10 + t] = o;
    }
}

// ---------------- launch ----------------
extern "C" void kernel_launch(void* const* d_in, const int* in_sizes, int n_in,
                              void* d_out, int out_size) {
    const float* x     = (const float*)d_in[0];
    const int*   ei    = (const int*)d_in[1];   // [2, E] int32
    const float* ew    = (const float*)d_in[2];
    const int*   batch = (const int*)d_in[3];   // [N] int32
    const float* W1    = (const float*)d_in[4];
    const float* b1    = (const float*)d_in[5];
    const float* W2    = (const float*)d_in[6];
    const float* b2    = (const float*)d_in[7];
    const float* LW1   = (const float*)d_in[8];
    const float* Lb1   = (const float*)d_in[9];
    const float* LW2   = (const float*)d_in[10];
    const float* Lb2   = (const float*)d_in[11];
    float* out = (float*)d_out;

    const int* src = ei;
    const int* dst = ei + N_EDGES;

    void *p_deg, *p_pool, *p_cnt;
    cudaGetSymbolAddress(&p_deg,  g_deg);
    cudaGetSymbolAddress(&p_pool, g_pool);
    cudaGetSymbolAddress(&p_cnt,  g_cnt);
    cudaMemsetAsync(p_deg,  0, N_NODES * sizeof(float));
    cudaMemsetAsync(p_pool, 0, N_GRAPHS * HID * sizeof(float));
    cudaMemsetAsync(p_cnt,  0, N_GRAPHS * sizeof(float));

    // degree & normalization coefficients
    deg_kernel<<<(N_EDGES + 255) / 256, 256>>>(dst, ew);
    dinv_kernel<<<(N_NODES + 255) / 256, 256>>>();
    coef_kernel<<<(N_EDGES + 255) / 256, 256>>>(src, dst, ew);

    float *xw, *h2;
    cudaGetSymbolAddress((void**)&xw, g_xw);
    cudaGetSymbolAddress((void**)&h2, g_h2);
    float *h1, *h3;
    cudaGetSymbolAddress((void**)&h1, g_h1);
    cudaGetSymbolAddress((void**)&h3, g_h3);

    // conv1: gemm (+fused self-loop/bias) then edge scatter
    gemm1_kernel<<<N_NODES / G1_ROWS + (N_NODES % G1_ROWS != 0), 256>>>(x, W1, b1);
    scatter_kernel<<<(N_EDGES * 16 + 255) / 256, 256>>>(src, dst, xw, h1);

    // conv2 (relu fused into gemm2's operand load)
    gemm2_kernel<<<N_NODES / G1_ROWS + (N_NODES % G1_ROWS != 0), 256>>>(W2, b2);
    scatter_kernel<<<(N_EDGES * 16 + 255) / 256, 256>>>(src, dst, h2, h3);

    // pooling + head
    pool_kernel<<<(N_NODES * 16 + 255) / 256, 256>>>(batch);
    head_kernel<<<N_GRAPHS, 32>>>(LW1, Lb1, LW2, Lb2, out);
}

// round 4
// speedup vs baseline: 2.4579x; 1.3330x over previous
#include <cuda_runtime.h>
#include <cuda_bf16.h>

#define N_NODES 50000
#define N_EDGES 800000
#define N_GRAPHS 512
#define IN_CH 128
#define HID 64     // HID_CH == OUT_CH == 64

// ---------------- scratch (device globals; no allocs allowed) ----------------
__device__ float g_xw[N_NODES * HID];    // x @ W1
__device__ float g_h1[N_NODES * HID];    // conv1 out (pre-relu)
__device__ float g_h2[N_NODES * HID];    // relu(h1) @ W2
__device__ float g_h3[N_NODES * HID];    // conv2 out
__device__ float g_deg[N_NODES];
__device__ float g_dinv[N_NODES];
__device__ float g_coef[N_EDGES];
__device__ float g_pool[N_GRAPHS * HID];
__device__ float g_cnt[N_GRAPHS];

// vectorized fp32 reduction (sm_90+): one L2 atomic op per 16 bytes
__device__ __forceinline__ void red_add_v4(float* addr, float a, float b,
                                           float c, float d) {
    asm volatile("red.global.add.v4.f32 [%0], {%1, %2, %3, %4};"
                 :: "l"(addr), "f"(a), "f"(b), "f"(c), "f"(d) : "memory");
}

// ---------------- degree / norm ----------------
__global__ void deg_kernel(const int* __restrict__ dst,
                           const float* __restrict__ ew) {
    int e = blockIdx.x * blockDim.x + threadIdx.x;
    if (e < N_EDGES) atomicAdd(&g_deg[dst[e]], ew[e]);
}

__global__ void dinv_kernel() {
    int i = blockIdx.x * blockDim.x + threadIdx.x;
    if (i < N_NODES) {
        float d = g_deg[i] + 1.0f;  // +1 self loop; always > 0
        g_dinv[i] = rsqrtf(d);
    }
}

__global__ void coef_kernel(const int* __restrict__ src,
                            const int* __restrict__ dst,
                            const float* __restrict__ ew) {
    int e = blockIdx.x * blockDim.x + threadIdx.x;
    if (e < N_EDGES) {
        g_coef[e] = g_dinv[src[e]] * ew[e] * g_dinv[dst[e]];
    }
}

// ---------------- GEMM 1: [N,128] @ [128,64] -> g_xw, g_h1 ------------------
// 64x64 tile, 256 threads, 4 rows x 4 cols per thread. Dynamic smem (66.8KB).
#define TM 64
#define XS1_LD 132   // padded float stride; 132*4 bytes, 16B-aligned rows
__global__ void gemm1_kernel(const float* __restrict__ x,
                             const float* __restrict__ W,
                             const float* __restrict__ b) {
    extern __shared__ float sm1[];
    float* Ws = sm1;                    // [128*64]
    float* Xs = sm1 + IN_CH * HID;      // [64 * XS1_LD]
    int tid = threadIdx.x;
    int row0 = blockIdx.x * TM;

    for (int i = tid; i < IN_CH * HID / 4; i += 256)
        *(float4*)&Ws[i * 4] = *(const float4*)&W[i * 4];
    // stage 64 rows of x (float4 per thread-iter)
    for (int i = tid; i < TM * (IN_CH / 4); i += 256) {
        int r  = i >> 5;            // 32 float4 per row
        int c4 = (i & 31) * 4;
        int node = row0 + r;
        float4 v = (node < N_NODES)
                 ? *(const float4*)&x[(long long)node * IN_CH + c4]
                 : make_float4(0.f, 0.f, 0.f, 0.f);
        *(float4*)&Xs[r * XS1_LD + c4] = v;
    }
    __syncthreads();

    int ty = tid >> 4;            // 0..15 -> rows ty*4..ty*4+3
    int tx = tid & 15;            // 0..15 -> cols tx*4..tx*4+3
    float4 acc0 = make_float4(0,0,0,0), acc1 = acc0, acc2 = acc0, acc3 = acc0;
    const float* xrow = &Xs[(ty * 4) * XS1_LD];
    #pragma unroll 4
    for (int k = 0; k < IN_CH; k++) {
        float4 w = *(const float4*)&Ws[k * HID + tx * 4];
        float x0 = xrow[k];
        float x1 = xrow[XS1_LD + k];
        float x2 = xrow[2 * XS1_LD + k];
        float x3 = xrow[3 * XS1_LD + k];
        acc0.x += x0*w.x; acc0.y += x0*w.y; acc0.z += x0*w.z; acc0.w += x0*w.w;
        acc1.x += x1*w.x; acc1.y += x1*w.y; acc1.z += x1*w.z; acc1.w += x1*w.w;
        acc2.x += x2*w.x; acc2.y += x2*w.y; acc2.z += x2*w.z; acc2.w += x2*w.w;
        acc3.x += x3*w.x; acc3.y += x3*w.y; acc3.z += x3*w.z; acc3.w += x3*w.w;
    }
    float4 bb = *(const float4*)&b[tx * 4];
    float4 accs[4] = {acc0, acc1, acc2, acc3};
    #pragma unroll
    for (int i = 0; i < 4; i++) {
        int node = row0 + ty * 4 + i;
        if (node < N_NODES) {
            *(float4*)&g_xw[node * HID + tx * 4] = accs[i];
            float d = g_dinv[node];
            float dd = d * d;
            float4 h = make_float4(dd*accs[i].x + bb.x, dd*accs[i].y + bb.y,
                                   dd*accs[i].z + bb.z, dd*accs[i].w + bb.w);
            *(float4*)&g_h1[node * HID + tx * 4] = h;
        }
    }
}

// ---------------- GEMM 2: relu(g_h1) [N,64] @ [64,64] -> g_h2, g_h3 ---------
#define XS2_LD 68
__global__ void gemm2_kernel(const float* __restrict__ W,
                             const float* __restrict__ b) {
    __shared__ float Ws[HID * HID];        // 16 KB
    __shared__ float Xs[TM * XS2_LD];      // 17.4 KB
    int tid = threadIdx.x;
    int row0 = blockIdx.x * TM;

    for (int i = tid; i < HID * HID / 4; i += 256)
        *(float4*)&Ws[i * 4] = *(const float4*)&W[i * 4];
    for (int i = tid; i < TM * (HID / 4); i += 256) {
        int r  = i >> 4;            // 16 float4 per row
        int c4 = (i & 15) * 4;
        int node = row0 + r;
        float4 v = make_float4(0.f, 0.f, 0.f, 0.f);
        if (node < N_NODES) {
            float4 t = *(const float4*)&g_h1[node * HID + c4];
            v = make_float4(fmaxf(t.x, 0.f), fmaxf(t.y, 0.f),
                            fmaxf(t.z, 0.f), fmaxf(t.w, 0.f));
        }
        *(float4*)&Xs[r * XS2_LD + c4] = v;
    }
    __syncthreads();

    int ty = tid >> 4;
    int tx = tid & 15;
    float4 acc0 = make_float4(0,0,0,0), acc1 = acc0, acc2 = acc0, acc3 = acc0;
    const float* xrow = &Xs[(ty * 4) * XS2_LD];
    #pragma unroll 4
    for (int k = 0; k < HID; k++) {
        float4 w = *(const float4*)&Ws[k * HID + tx * 4];
        float x0 = xrow[k];
        float x1 = xrow[XS2_LD + k];
        float x2 = xrow[2 * XS2_LD + k];
        float x3 = xrow[3 * XS2_LD + k];
        acc0.x += x0*w.x; acc0.y += x0*w.y; acc0.z += x0*w.z; acc0.w += x0*w.w;
        acc1.x += x1*w.x; acc1.y += x1*w.y; acc1.z += x1*w.z; acc1.w += x1*w.w;
        acc2.x += x2*w.x; acc2.y += x2*w.y; acc2.z += x2*w.z; acc2.w += x2*w.w;
        acc3.x += x3*w.x; acc3.y += x3*w.y; acc3.z += x3*w.z; acc3.w += x3*w.w;
    }
    float4 bb = *(const float4*)&b[tx * 4];
    float4 accs[4] = {acc0, acc1, acc2, acc3};
    #pragma unroll
    for (int i = 0; i < 4; i++) {
        int node = row0 + ty * 4 + i;
        if (node < N_NODES) {
            *(float4*)&g_h2[node * HID + tx * 4] = accs[i];
            float d = g_dinv[node];
            float dd = d * d;
            float4 h = make_float4(dd*accs[i].x + bb.x, dd*accs[i].y + bb.y,
                                   dd*accs[i].z + bb.z, dd*accs[i].w + bb.w);
            *(float4*)&g_h3[node * HID + tx * 4] = h;
        }
    }
}

// ---------------- edge scatter: out[dst] += coef * in[src] ------------------
__global__ void scatter_kernel(const int* __restrict__ src,
                               const int* __restrict__ dst,
                               const float* __restrict__ in,
                               float* __restrict__ out) {
    int idx = blockIdx.x * blockDim.x + threadIdx.x;   // < 12.8M
    if (idx >= N_EDGES * 16) return;
    int e  = idx >> 4;
    int c4 = (idx & 15) * 4;
    float cf = g_coef[e];
    int s = src[e];
    int d = dst[e];
    float4 v = *(const float4*)(in + (long long)s * HID + c4);
    red_add_v4(out + (long long)d * HID + c4,
               cf * v.x, cf * v.y, cf * v.z, cf * v.w);
}

// ---------------- pooling: segment mean over graphs -------------------------
__global__ void pool_kernel(const int* __restrict__ batch) {
    int idx = blockIdx.x * blockDim.x + threadIdx.x;   // < 800k
    if (idx < N_NODES * 16) {
        int i  = idx >> 4;
        int c4 = (idx & 15) * 4;
        int g = batch[i];
        float4 v = *(const float4*)&g_h3[i * HID + c4];
        red_add_v4(&g_pool[g * HID + c4], v.x, v.y, v.z, v.w);
        if (c4 == 0) atomicAdd(&g_cnt[g], 1.0f);
    }
}

// ---------------- head ----------------
__global__ void head_kernel(const float* __restrict__ LW1,
                            const float* __restrict__ Lb1,
                            const float* __restrict__ LW2,
                            const float* __restrict__ Lb2,
                            float* __restrict__ out) {
    int g = blockIdx.x;
    int t = threadIdx.x;  // 32 threads
    __shared__ float p[HID];
    __shared__ float h[32];
    float cnt = fmaxf(g_cnt[g], 1.0f);
    p[t]      = g_pool[g * HID + t] / cnt;
    p[t + 32] = g_pool[g * HID + 32 + t] / cnt;
    __syncwarp();
    float acc = Lb1[t];
    #pragma unroll
    for (int k = 0; k < HID; k++) acc += p[k] * LW1[k * 32 + t];
    h[t] = acc;
    __syncwarp();
    if (t < 10) {
        float o = Lb2[t];
        #pragma unroll
        for (int j = 0; j < 32; j++) o += h[j] * LW2[j * 10 + t];
        out[g * 10 + t] = o;
    }
}

// ---------------- launch ----------------
extern "C" void kernel_launch(void* const* d_in, const int* in_sizes, int n_in,
                              void* d_out, int out_size) {
    const float* x     = (const float*)d_in[0];
    const int*   ei    = (const int*)d_in[1];   // [2, E] int32
    const float* ew    = (const float*)d_in[2];
    const int*   batch = (const int*)d_in[3];   // [N] int32
    const float* W1    = (const float*)d_in[4];
    const float* b1    = (const float*)d_in[5];
    const float* W2    = (const float*)d_in[6];
    const float* b2    = (const float*)d_in[7];
    const float* LW1   = (const float*)d_in[8];
    const float* Lb1   = (const float*)d_in[9];
    const float* LW2   = (const float*)d_in[10];
    const float* Lb2   = (const float*)d_in[11];
    float* out = (float*)d_out;

    const int* src = ei;
    const int* dst = ei + N_EDGES;

    void *p_deg, *p_pool, *p_cnt;
    cudaGetSymbolAddress(&p_deg,  g_deg);
    cudaGetSymbolAddress(&p_pool, g_pool);
    cudaGetSymbolAddress(&p_cnt,  g_cnt);
    cudaMemsetAsync(p_deg,  0, N_NODES * sizeof(float));
    cudaMemsetAsync(p_pool, 0, N_GRAPHS * HID * sizeof(float));
    cudaMemsetAsync(p_cnt,  0, N_GRAPHS * sizeof(float));

    // degree & normalization coefficients
    deg_kernel<<<(N_EDGES + 255) / 256, 256>>>(dst, ew);
    dinv_kernel<<<(N_NODES + 255) / 256, 256>>>();
    coef_kernel<<<(N_EDGES + 255) / 256, 256>>>(src, dst, ew);

    float *xw, *h1, *h2, *h3;
    cudaGetSymbolAddress((void**)&xw, g_xw);
    cudaGetSymbolAddress((void**)&h1, g_h1);
    cudaGetSymbolAddress((void**)&h2, g_h2);
    cudaGetSymbolAddress((void**)&h3, g_h3);

    const int SM1_BYTES = (IN_CH * HID + TM * XS1_LD) * (int)sizeof(float);
    static bool attr_set = false;
    if (!attr_set) {
        cudaFuncSetAttribute(gemm1_kernel,
                             cudaFuncAttributeMaxDynamicSharedMemorySize,
                             SM1_BYTES);
        attr_set = true;
    }

    int gblocks = (N_NODES + TM - 1) / TM;

    // conv1: gemm (+fused self-loop/bias) then edge scatter
    gemm1_kernel<<<gblocks, 256, SM1_BYTES>>>(x, W1, b1);
    scatter_kernel<<<(N_EDGES * 16 + 255) / 256, 256>>>(src, dst, xw, h1);

    // conv2 (relu fused at staging)
    gemm2_kernel<<<gblocks, 256>>>(W2, b2);
    scatter_kernel<<<(N_EDGES * 16 + 255) / 256, 256>>>(src, dst, h2, h3);

    // pooling + head
    pool_kernel<<<(N_NODES * 16 + 255) / 256, 256>>>(batch);
    head_kernel<<<N_GRAPHS, 32>>>(LW1, Lb1, LW2, Lb2, out);
}